// round 12
// baseline (speedup 1.0000x reference)
#include <cuda_runtime.h>
#include <cuda_fp16.h>
#include <math.h>
#include <complex>
#include <cstring>
#include <cstdint>

// ============================================================================
// FullyConnectedTensorProduct via fused warp-level mma.sync fp16 GEMM.
//   M-tile = 64 rows of (n,k); D[r,w] += sum_paths A_p[r,u] * Wt_p[w,u]
//   Single fp16 term Ah*Wh (rel ~2.9e-4 vs 1e-3 threshold).
//   R11: quad-u producer (4 u's x 8 rows per thread, warp-wide row groups)
//   -> ~28% fewer produce instructions, warp-coalesced x1 loads, STS.64.
//   52 KB smem -> 4 CTAs/SM; 256 threads, 8 warps (2x4), 32x32 warp tile.
// ============================================================================

#define NPATHS 11

// ---- smem layout (bytes) ---------------------------------------------------
#define CT_OFF    0          // c-table (<= 1024 floats)
#define AH_OFF    4096       // 16 KB A hi tile (64 r x 128 u fp16, swizzled)
#define B_OFF     20480      // 32 KB B tile (128 w x 128 u fp16, swizzled)
#define SMEM_TOTAL 53248
#define EPI_OFF   4096       // epilogue transpose buffer reuses A+B region

__device__ __align__(16) __half g_B[NPATHS][16384];   // hi plane only

struct Params {
    float C[363];       // w3j tensors, scaled by PW[lo]
    int4  cmap[115];    // {Cstart, nj, jstride, x2off}, grouped lo0|lo1|lo2
    int   cmap_off[3];
};

// compile-time per-lo path tables (must match build_params cmap ordering)
struct LoCfg { int np, nc; int l1[4]; int cb[4]; int gid[4]; };
__device__ __constant__ const LoCfg kCfg[3] = {
    {3,  9, {0,1,2,0}, {0,1,4,0},   {0,4,9,0}},
    {4, 36, {0,1,1,2}, {0,3,12,21}, {1,3,6,8}},
    {4, 70, {0,1,2,2}, {0,5,20,45}, {2,5,7,10}},
};

// ---- PTX helpers -----------------------------------------------------------
__device__ __forceinline__ uint32_t smem_u32(const void* p) {
    uint32_t a;
    asm("{ .reg .u64 t; cvta.to.shared.u64 t, %1; cvt.u32.u64 %0, t; }"
        : "=r"(a) : "l"(p));
    return a;
}
__device__ __forceinline__ void cpasync16(uint32_t dst, const void* src) {
    asm volatile("cp.async.cg.shared.global [%0], [%1], 16;"
                 :: "r"(dst), "l"(src) : "memory");
}
#define LDSM4(R, ADDR)                                                        \
    asm volatile("ldmatrix.sync.aligned.m8n8.x4.shared.b16 "                  \
                 "{%0,%1,%2,%3}, [%4];"                                       \
                 : "=r"((R)[0]), "=r"((R)[1]), "=r"((R)[2]), "=r"((R)[3])     \
                 : "r"(ADDR))
#define MMA(D, A, B0, B1)                                                     \
    asm volatile("mma.sync.aligned.m16n8k16.row.col.f32.f16.f16.f32 "         \
                 "{%0,%1,%2,%3}, {%4,%5,%6,%7}, {%8,%9}, {%0,%1,%2,%3};"      \
                 : "+f"((D)[0]), "+f"((D)[1]), "+f"((D)[2]), "+f"((D)[3])     \
                 : "r"((A)[0]), "r"((A)[1]), "r"((A)[2]), "r"((A)[3]),        \
                   "r"(B0), "r"(B1))

// swizzled byte offset of (row, half-col u) in a [rows]x128 fp16 tile
__device__ __host__ __forceinline__ uint32_t swz(int row, int u) {
    return (uint32_t)row * 256u
         + (uint32_t)(((u >> 3) ^ (row & 7)) << 4)
         + (uint32_t)((u & 7) * 2);
}

// ============================================================================
// wprep: weights -> fp16 hi, transposed [w][u], pre-swizzled tiles
// ============================================================================
__global__ void wprep_kernel(const float* __restrict__ wt) {
    const int gid = blockIdx.x;
    const float* wp = wt + (size_t)gid * 16384;
    for (int idx = threadIdx.x; idx < 16384; idx += blockDim.x) {
        int u = idx >> 7, w = idx & 127;
        g_B[gid][swz(w, u) >> 1] = __float2half_rn(wp[u * 128 + w]);
    }
}

// ---- produce A (hi plane), quad-u: 4 u's x 8 rows per thread ---------------
template<int D1, int DL, int NC>
__device__ __forceinline__ void produceA(
    const float* __restrict__ x1, const float* __restrict__ ct, char* smem,
    int m0, int r0p, int u0, int n_lo, int Ntot, int xo, int cbase)
{
    int n = (m0 + r0p) / DL;
    int k = (m0 + r0p) - n * DL;
    float xv[4][D1];
    bool fresh = true;
    #pragma unroll 2
    for (int rr = 0; rr < 8; rr++) {
        uint32_t h01 = 0, h23 = 0;
        if (n < Ntot) {
            if (fresh) {
                const float* xb = x1 + (size_t)n * 1152 + xo + D1 * u0;
                #pragma unroll
                for (int q = 0; q < 4; q++)
                    #pragma unroll
                    for (int i = 0; i < D1; i++)
                        xv[q][i] = xb[q * D1 + i];
                fresh = false;
            }
            const float* cr = ct + (n - n_lo) * NC + cbase + k;
            float s0 = 0.f, s1 = 0.f, s2 = 0.f, s3 = 0.f;
            #pragma unroll
            for (int i = 0; i < D1; i++) {
                float cc = cr[i * DL];
                s0 += xv[0][i] * cc;
                s1 += xv[1][i] * cc;
                s2 += xv[2][i] * cc;
                s3 += xv[3][i] * cc;
            }
            __half2 a = __floats2half2_rn(s0, s1);
            __half2 b = __floats2half2_rn(s2, s3);
            h01 = *(uint32_t*)&a;
            h23 = *(uint32_t*)&b;
        }
        // u0 % 4 == 0 -> (u0&7)*2 in {0,8} -> 8B-aligned, contiguous quad
        *(uint2*)(smem + AH_OFF + swz(r0p + rr, u0)) = make_uint2(h01, h23);
        if (++k == DL) { k = 0; n++; fresh = true; }
    }
}

// ============================================================================
// templated CTA body: all lo-dependent constants compile-time
// ============================================================================
template<int LO>
__device__ __forceinline__ void body(
    int mt_idx, const float* __restrict__ x1, const float* __restrict__ x2,
    float* __restrict__ out, int Ntot, const Params& P, char* smem)
{
    constexpr int DL = 2 * LO + 1;
    constexpr int NC = (LO == 0) ? 9 : (LO == 1) ? 36 : 70;
    constexpr int NP = (LO == 0) ? 3 : 4;
    constexpr int OB = (LO == 0) ? 0 : (LO == 1) ? 128 : 512;

    const uint32_t sb = smem_u32(smem);
    float* ct = (float*)(smem + CT_OFF);
    const int tid  = threadIdx.x;
    const int wid  = tid >> 5;
    const int lane = tid & 31;

    const int m0 = mt_idx * 64;
    const int n_lo = m0 / DL;
    int n_hi = (m0 + 63) / DL;
    if (n_hi > Ntot - 1) n_hi = Ntot - 1;
    const int n_count = n_hi - n_lo + 1;

    // ---- prefetch B(path 0) ------------------------------------------------
    {
        const int gid = kCfg[LO].gid[0];
        for (int c = tid; c < 2048; c += 256)
            cpasync16(sb + B_OFF + c * 16, (const char*)g_B[gid] + c * 16);
        asm volatile("cp.async.commit_group;" ::: "memory");
    }

    // ---- phase 0: c-table --------------------------------------------------
    {
        const int cm0 = P.cmap_off[LO];
        const int tot = n_count * NC;
        for (int t = tid; t < tot; t += 256) {
            int ni = t / NC, e = t - ni * NC;      // NC compile-time
            int n = n_lo + ni;
            float s = 0.f;
            if (n < Ntot) {
                int4 m = P.cmap[cm0 + e];
                const float* xr = x2 + (size_t)n * 9 + m.w;
                for (int j = 0; j < m.y; j++) s += P.C[m.x + j * m.z] * xr[j];
            }
            ct[t] = s;
        }
    }
    __syncthreads();

    // ---- warp tiling: 2x4 grid, warp = 32M x 32N --------------------------
    const int mrow0 = (wid >> 2) * 32;
    const int ncol0 = (wid & 3) * 32;
    const int lrow  = lane & 15;
    const int khalf = lane >> 4;

    uint32_t aRow[2]; int a7[2];
    #pragma unroll
    for (int mt = 0; mt < 2; mt++) {
        int r = mrow0 + mt * 16 + lrow;
        aRow[mt] = (uint32_t)r * 256u;
        a7[mt] = r & 7;
    }
    uint32_t bRow[2]; int b7[2];
    #pragma unroll
    for (int p = 0; p < 2; p++) {
        int r = ncol0 + p * 16 + lrow;
        bRow[p] = (uint32_t)r * 256u;
        b7[p] = r & 7;
    }

    float acc[2][4][4];
    #pragma unroll
    for (int i = 0; i < 2; i++)
        #pragma unroll
        for (int j = 0; j < 4; j++)
            #pragma unroll
            for (int c = 0; c < 4; c++) acc[i][j][c] = 0.f;

    const int u0  = 4 * (tid & 31);      // A-producer u quad (warp spans all u)
    const int r0p = (tid >> 5) * 8;      // A-producer row group (8 rows, per warp)

    // ---- path loop ---------------------------------------------------------
    #pragma unroll
    for (int pi = 0; pi < NP; pi++) {
        {
            const int l1 = kCfg[LO].l1[pi];
            const int cbase = kCfg[LO].cb[pi];
            if (l1 == 0)
                produceA<1, DL, NC>(x1, ct, smem, m0, r0p, u0, n_lo, Ntot, 0, cbase);
            else if (l1 == 1)
                produceA<3, DL, NC>(x1, ct, smem, m0, r0p, u0, n_lo, Ntot, 128, cbase);
            else
                produceA<5, DL, NC>(x1, ct, smem, m0, r0p, u0, n_lo, Ntot, 512, cbase);
        }

        asm volatile("cp.async.wait_group 0;" ::: "memory");
        __syncthreads();   // A(pi) + B(pi) ready for all warps

        // ---- MMA(pi): 8 k-steps, single term ------------------------------
        #pragma unroll 1
        for (int ks = 0; ks < 8; ks++) {
            const int ch = 2 * ks + khalf;
            uint32_t ah[2][4], bh[2][4];
            #pragma unroll
            for (int mt = 0; mt < 2; mt++)
                LDSM4(ah[mt], sb + AH_OFF + aRow[mt] + (uint32_t)((ch ^ a7[mt]) << 4));
            #pragma unroll
            for (int p = 0; p < 2; p++)
                LDSM4(bh[p], sb + B_OFF + bRow[p] + (uint32_t)((ch ^ b7[p]) << 4));
            #pragma unroll
            for (int mt = 0; mt < 2; mt++)
                #pragma unroll
                for (int p = 0; p < 2; p++) {
                    MMA(acc[mt][2*p],   ah[mt], bh[p][0], bh[p][2]);
                    MMA(acc[mt][2*p+1], ah[mt], bh[p][1], bh[p][3]);
                }
        }

        __syncthreads();   // all warps done reading A(pi), B(pi)

        if (pi + 1 < NP) {  // refill B for next path (overlaps next produce)
            const int gid2 = kCfg[LO].gid[pi + 1];
            for (int c = tid; c < 2048; c += 256)
                cpasync16(sb + B_OFF + c * 16, (const char*)g_B[gid2] + c * 16);
            asm volatile("cp.async.commit_group;" ::: "memory");
        }
    }

    // ---- epilogue: acc -> smem [w][r] transpose -> coalesced stores --------
    float* sepi = (float*)(smem + EPI_OFF);
    {
        const int arow = lane >> 2;
        const int acol = (lane & 3) * 2;
        #pragma unroll
        for (int mt = 0; mt < 2; mt++)
            #pragma unroll
            for (int nt = 0; nt < 4; nt++)
                #pragma unroll
                for (int c = 0; c < 4; c++) {
                    int r = mrow0 + mt * 16 + arow + ((c >> 1) << 3);
                    int w = ncol0 + nt * 8 + acol + (c & 1);
                    sepi[w * 68 + r] = acc[mt][nt][c];
                }
    }
    __syncthreads();

    constexpr int WDL = 128 * DL;
    const int tot = n_count * WDL;
    for (int e = tid; e < tot; e += 256) {
        int ni = e / WDL, o = e - ni * WDL;    // compile-time divisors
        int wq = o / DL, k = o - wq * DL;
        int n = n_lo + ni;
        int r = n * DL + k - m0;
        if (n < Ntot && r >= 0 && r < 64)
            out[(size_t)n * 1152 + OB + o] = sepi[wq * 68 + r];
    }
}

// ============================================================================
// fused GEMM kernel: dispatch on lo, then fully-templated body
// ============================================================================
__global__ __launch_bounds__(256, 4)
void fctp_gemm(const float* __restrict__ x1, const float* __restrict__ x2,
               float* __restrict__ out, int Ntot, int T0, int T1,
               const __grid_constant__ Params P)
{
    extern __shared__ char smem[];
    const int b = blockIdx.x;
    if (b < T0)           body<0>(b,            x1, x2, out, Ntot, P, smem);
    else if (b < T0 + T1) body<1>(b - T0,       x1, x2, out, Ntot, P, smem);
    else                  body<2>(b - T0 - T1,  x1, x2, out, Ntot, P, smem);
}

// ============================================================================
// Host: Wigner-3j construction (fp64, identical math to the reference)
// ============================================================================
typedef std::complex<double> cd;

static double factd(int n) { double r = 1; for (int i = 2; i <= n; i++) r *= i; return r; }

static double su2cg(int j1, int m1, int j2, int m2, int j3, int m3) {
    if (m3 != m1 + m2) return 0.0;
    int vmin = -j1 + j2 + m3; if (-j1 + m1 > vmin) vmin = -j1 + m1; if (0 > vmin) vmin = 0;
    int vmax = j2 + j3 + m1; if (j3 - j1 + j2 < vmax) vmax = j3 - j1 + j2; if (j3 + m3 < vmax) vmax = j3 + m3;
    if (vmax < vmin) return 0.0;
    double pref = (2.0 * j3 + 1.0) *
        (factd(j3 + j1 - j2) * factd(j3 - j1 + j2) * factd(j1 + j2 - j3) *
         factd(j3 + m3) * factd(j3 - m3)) /
        (factd(j1 + j2 + j3 + 1) * factd(j1 - m1) * factd(j1 + m1) *
         factd(j2 - m2) * factd(j2 + m2));
    double S = 0.0;
    for (int v = vmin; v <= vmax; v++) {
        int par = v + j2 + m2;
        double sgn = (((par % 2) + 2) % 2) ? -1.0 : 1.0;
        S += sgn * (factd(j2 + j3 + m1 - v) * factd(j1 - m1 + v)) /
             (factd(v) * factd(j3 - j1 + j2 - v) * factd(j3 + m3 - v) *
              factd(v + j1 - j2 - m3));
    }
    return sqrt(pref) * S;
}

static void calcq(int l, cd q[5][5]) {
    for (int a = 0; a < 5; a++) for (int b = 0; b < 5; b++) q[a][b] = cd(0, 0);
    const double s2 = 1.0 / sqrt(2.0);
    for (int m = -l; m < 0; m++) {
        q[l + m][l - m] = cd(s2, 0);
        q[l + m][l + m] = cd(0, -s2);
    }
    q[l][l] = cd(1, 0);
    for (int m = 1; m <= l; m++) {
        double sg = (m % 2) ? -1.0 : 1.0;
        q[l + m][l + m] = cd(sg * s2, 0);
        q[l + m][l - m] = cd(0, sg * s2);
    }
    cd f = (l == 0) ? cd(1, 0) : (l == 1) ? cd(0, -1) : cd(-1, 0); // (-i)^l
    for (int a = 0; a < 5; a++) for (int b = 0; b < 5; b++) q[a][b] *= f;
}

static void calc_w3j(int l1, int l2, int l3, double* outv) {
    int d1 = 2 * l1 + 1, d2 = 2 * l2 + 1, d3 = 2 * l3 + 1;
    double C[5][5][5];
    memset(C, 0, sizeof(C));
    for (int m1 = -l1; m1 <= l1; m1++)
        for (int m2 = -l2; m2 <= l2; m2++) {
            int m3 = m1 + m2;
            if (m3 >= -l3 && m3 <= l3)
                C[m1 + l1][m2 + l2][m3 + l3] = su2cg(l1, m1, l2, m2, l3, m3);
        }
    cd Q1[5][5], Q2[5][5], Q3[5][5];
    calcq(l1, Q1); calcq(l2, Q2); calcq(l3, Q3);
    static cd Cc[5][5][5];
    for (int j = 0; j < d1; j++)
        for (int l = 0; l < d2; l++)
            for (int m = 0; m < d3; m++) {
                cd s(0, 0);
                for (int i = 0; i < d1; i++)
                    for (int k = 0; k < d2; k++)
                        for (int n = 0; n < d3; n++)
                            s += Q1[i][j] * Q2[k][l] * std::conj(Q3[n][m]) * C[i][k][n];
                Cc[j][l][m] = s;
            }
    double nr = 0, ni = 0;
    for (int j = 0; j < d1; j++)
        for (int l = 0; l < d2; l++)
            for (int m = 0; m < d3; m++) {
                nr += Cc[j][l][m].real() * Cc[j][l][m].real();
                ni += Cc[j][l][m].imag() * Cc[j][l][m].imag();
            }
    bool useR = sqrt(nr) >= sqrt(ni);
    double nrm = sqrt(useR ? nr : ni);
    for (int j = 0; j < d1; j++)
        for (int l = 0; l < d2; l++)
            for (int m = 0; m < d3; m++)
                outv[(j * d2 + l) * d3 + m] =
                    (useR ? Cc[j][l][m].real() : Cc[j][l][m].imag()) / nrm;
}

static void build_params(Params& P) {
    static const int L1[NPATHS]   = {0,0,0,1,1,1,1,2,2,2,2};
    static const int L2[NPATHS]   = {0,1,2,0,1,1,2,0,1,2,2};
    static const int LOA[NPATHS]  = {0,1,2,1,0,2,1,2,1,0,2};
    static const int cof3[NPATHS] = {0,1,10,35,44,53,98,143,168,213,238};
    static const int x2off[3] = {0, 1, 4};
    const double pw[3] = { sqrt(1.0/384.0), sqrt(3.0/512.0), sqrt(5.0/512.0) };

    for (int p = 0; p < NPATHS; p++) {
        int d1 = 2*L1[p] + 1, d2 = 2*L2[p] + 1, d3 = 2*LOA[p] + 1;
        double buf[125];
        calc_w3j(L1[p], L2[p], LOA[p], buf);
        for (int idx = 0; idx < d1*d2*d3; idx++)
            P.C[cof3[p] + idx] = (float)(buf[idx] * pw[LOA[p]]);
    }
    int ci = 0;
    for (int lo = 0; lo < 3; lo++) {
        P.cmap_off[lo] = ci;
        int d3 = 2*lo + 1;
        for (int gid = 0; gid < NPATHS; gid++) {
            if (LOA[gid] != lo) continue;
            int d1 = 2*L1[gid] + 1, d2 = 2*L2[gid] + 1;
            for (int i = 0; i < d1; i++)
                for (int k = 0; k < d3; k++)
                    P.cmap[ci++] = make_int4(cof3[gid] + i*d2*d3 + k, d2, d3,
                                             x2off[L2[gid]]);
        }
    }
}

extern "C" void kernel_launch(void* const* d_in, const int* in_sizes, int n_in,
                              void* d_out, int out_size)
{
    const float* x1  = (const float*)d_in[0];
    const float* x2  = (const float*)d_in[1];
    const float* wt  = (const float*)d_in[2];
    float*       out = (float*)d_out;
    const int N = in_sizes[0] / 1152;

    Params P;
    build_params(P);

    cudaFuncSetAttribute(fctp_gemm,
                         cudaFuncAttributeMaxDynamicSharedMemorySize, SMEM_TOTAL);

    wprep_kernel<<<NPATHS, 256>>>(wt);

    const int T0 = (N     + 63) / 64;
    const int T1 = (3 * N + 63) / 64;
    const int T2 = (5 * N + 63) / 64;
    fctp_gemm<<<T0 + T1 + T2, 256, SMEM_TOTAL>>>(x1, x2, out, N, T0, T1, P);
}

// round 13
// speedup vs baseline: 1.0935x; 1.0935x over previous
#include <cuda_runtime.h>
#include <cuda_fp16.h>
#include <math.h>
#include <complex>
#include <cstring>
#include <cstdint>

// ============================================================================
// FullyConnectedTensorProduct via fused warp-level mma.sync fp16 GEMM.
//   M-tile = 64 rows of (n,k); D[r,w] += sum_paths A_p[r,u] * Wt_p[w,u]
//   Single fp16 term Ah*Wh (rel ~2.9e-4 vs 1e-3 threshold).
//   R12: quad-u producer (R11) + float4-vectorized x1 loads -> 4x fewer
//   x1 LDG instructions/wavefronts (fixes R11's L1tex regression).
//   52 KB smem -> 4 CTAs/SM; 256 threads, 8 warps (2x4), 32x32 warp tile.
// ============================================================================

#define NPATHS 11

// ---- smem layout (bytes) ---------------------------------------------------
#define CT_OFF    0          // c-table (<= 1024 floats)
#define AH_OFF    4096       // 16 KB A hi tile (64 r x 128 u fp16, swizzled)
#define B_OFF     20480      // 32 KB B tile (128 w x 128 u fp16, swizzled)
#define SMEM_TOTAL 53248
#define EPI_OFF   4096       // epilogue transpose buffer reuses A+B region

__device__ __align__(16) __half g_B[NPATHS][16384];   // hi plane only

struct Params {
    float C[363];       // w3j tensors, scaled by PW[lo]
    int4  cmap[115];    // {Cstart, nj, jstride, x2off}, grouped lo0|lo1|lo2
    int   cmap_off[3];
};

// compile-time per-lo path tables (must match build_params cmap ordering)
struct LoCfg { int np, nc; int l1[4]; int cb[4]; int gid[4]; };
__device__ __constant__ const LoCfg kCfg[3] = {
    {3,  9, {0,1,2,0}, {0,1,4,0},   {0,4,9,0}},
    {4, 36, {0,1,1,2}, {0,3,12,21}, {1,3,6,8}},
    {4, 70, {0,1,2,2}, {0,5,20,45}, {2,5,7,10}},
};

// ---- PTX helpers -----------------------------------------------------------
__device__ __forceinline__ uint32_t smem_u32(const void* p) {
    uint32_t a;
    asm("{ .reg .u64 t; cvta.to.shared.u64 t, %1; cvt.u32.u64 %0, t; }"
        : "=r"(a) : "l"(p));
    return a;
}
__device__ __forceinline__ void cpasync16(uint32_t dst, const void* src) {
    asm volatile("cp.async.cg.shared.global [%0], [%1], 16;"
                 :: "r"(dst), "l"(src) : "memory");
}
#define LDSM4(R, ADDR)                                                        \
    asm volatile("ldmatrix.sync.aligned.m8n8.x4.shared.b16 "                  \
                 "{%0,%1,%2,%3}, [%4];"                                       \
                 : "=r"((R)[0]), "=r"((R)[1]), "=r"((R)[2]), "=r"((R)[3])     \
                 : "r"(ADDR))
#define MMA(D, A, B0, B1)                                                     \
    asm volatile("mma.sync.aligned.m16n8k16.row.col.f32.f16.f16.f32 "         \
                 "{%0,%1,%2,%3}, {%4,%5,%6,%7}, {%8,%9}, {%0,%1,%2,%3};"      \
                 : "+f"((D)[0]), "+f"((D)[1]), "+f"((D)[2]), "+f"((D)[3])     \
                 : "r"((A)[0]), "r"((A)[1]), "r"((A)[2]), "r"((A)[3]),        \
                   "r"(B0), "r"(B1))

// swizzled byte offset of (row, half-col u) in a [rows]x128 fp16 tile
__device__ __host__ __forceinline__ uint32_t swz(int row, int u) {
    return (uint32_t)row * 256u
         + (uint32_t)(((u >> 3) ^ (row & 7)) << 4)
         + (uint32_t)((u & 7) * 2);
}

// ============================================================================
// wprep: weights -> fp16 hi, transposed [w][u], pre-swizzled tiles
// ============================================================================
__global__ void wprep_kernel(const float* __restrict__ wt) {
    const int gid = blockIdx.x;
    const float* wp = wt + (size_t)gid * 16384;
    for (int idx = threadIdx.x; idx < 16384; idx += blockDim.x) {
        int u = idx >> 7, w = idx & 127;
        g_B[gid][swz(w, u) >> 1] = __float2half_rn(wp[u * 128 + w]);
    }
}

// ---- produce A (hi plane), quad-u + float4 x1 loads ------------------------
// thread -> 4 u's (u0..u0+3) x 8 rows; fresh x1 load = D1 x LDG.128.
template<int D1, int DL, int NC>
__device__ __forceinline__ void produceA(
    const float* __restrict__ x1, const float* __restrict__ ct, char* smem,
    int m0, int r0p, int u0, int n_lo, int Ntot, int xo, int cbase)
{
    int n = (m0 + r0p) / DL;
    int k = (m0 + r0p) - n * DL;
    float xv[4 * D1];                 // xv[q*D1 + i] = x1[n, u0+q, i]
    bool fresh = true;
    #pragma unroll 2
    for (int rr = 0; rr < 8; rr++) {
        uint32_t h01 = 0, h23 = 0;
        if (n < Ntot) {
            if (fresh) {
                // 4*D1 contiguous floats, 16B-aligned -> D1 x float4
                const float4* xb4 = reinterpret_cast<const float4*>(
                    x1 + (size_t)n * 1152 + xo + D1 * u0);
                #pragma unroll
                for (int i4 = 0; i4 < D1; i4++) {
                    float4 v = xb4[i4];
                    xv[4 * i4 + 0] = v.x;
                    xv[4 * i4 + 1] = v.y;
                    xv[4 * i4 + 2] = v.z;
                    xv[4 * i4 + 3] = v.w;
                }
                fresh = false;
            }
            const float* cr = ct + (n - n_lo) * NC + cbase + k;
            float s0 = 0.f, s1 = 0.f, s2 = 0.f, s3 = 0.f;
            #pragma unroll
            for (int i = 0; i < D1; i++) {
                float cc = cr[i * DL];
                s0 += xv[0 * D1 + i] * cc;
                s1 += xv[1 * D1 + i] * cc;
                s2 += xv[2 * D1 + i] * cc;
                s3 += xv[3 * D1 + i] * cc;
            }
            __half2 a = __floats2half2_rn(s0, s1);
            __half2 b = __floats2half2_rn(s2, s3);
            h01 = *(uint32_t*)&a;
            h23 = *(uint32_t*)&b;
        }
        // u0 % 4 == 0 -> (u0&7)*2 in {0,8} -> 8B-aligned, contiguous quad
        *(uint2*)(smem + AH_OFF + swz(r0p + rr, u0)) = make_uint2(h01, h23);
        if (++k == DL) { k = 0; n++; fresh = true; }
    }
}

// ============================================================================
// templated CTA body: all lo-dependent constants compile-time
// ============================================================================
template<int LO>
__device__ __forceinline__ void body(
    int mt_idx, const float* __restrict__ x1, const float* __restrict__ x2,
    float* __restrict__ out, int Ntot, const Params& P, char* smem)
{
    constexpr int DL = 2 * LO + 1;
    constexpr int NC = (LO == 0) ? 9 : (LO == 1) ? 36 : 70;
    constexpr int NP = (LO == 0) ? 3 : 4;
    constexpr int OB = (LO == 0) ? 0 : (LO == 1) ? 128 : 512;

    const uint32_t sb = smem_u32(smem);
    float* ct = (float*)(smem + CT_OFF);
    const int tid  = threadIdx.x;
    const int wid  = tid >> 5;
    const int lane = tid & 31;

    const int m0 = mt_idx * 64;
    const int n_lo = m0 / DL;
    int n_hi = (m0 + 63) / DL;
    if (n_hi > Ntot - 1) n_hi = Ntot - 1;
    const int n_count = n_hi - n_lo + 1;

    // ---- prefetch B(path 0) ------------------------------------------------
    {
        const int gid = kCfg[LO].gid[0];
        for (int c = tid; c < 2048; c += 256)
            cpasync16(sb + B_OFF + c * 16, (const char*)g_B[gid] + c * 16);
        asm volatile("cp.async.commit_group;" ::: "memory");
    }

    // ---- phase 0: c-table --------------------------------------------------
    {
        const int cm0 = P.cmap_off[LO];
        const int tot = n_count * NC;
        for (int t = tid; t < tot; t += 256) {
            int ni = t / NC, e = t - ni * NC;      // NC compile-time
            int n = n_lo + ni;
            float s = 0.f;
            if (n < Ntot) {
                int4 m = P.cmap[cm0 + e];
                const float* xr = x2 + (size_t)n * 9 + m.w;
                for (int j = 0; j < m.y; j++) s += P.C[m.x + j * m.z] * xr[j];
            }
            ct[t] = s;
        }
    }
    __syncthreads();

    // ---- warp tiling: 2x4 grid, warp = 32M x 32N --------------------------
    const int mrow0 = (wid >> 2) * 32;
    const int ncol0 = (wid & 3) * 32;
    const int lrow  = lane & 15;
    const int khalf = lane >> 4;

    uint32_t aRow[2]; int a7[2];
    #pragma unroll
    for (int mt = 0; mt < 2; mt++) {
        int r = mrow0 + mt * 16 + lrow;
        aRow[mt] = (uint32_t)r * 256u;
        a7[mt] = r & 7;
    }
    uint32_t bRow[2]; int b7[2];
    #pragma unroll
    for (int p = 0; p < 2; p++) {
        int r = ncol0 + p * 16 + lrow;
        bRow[p] = (uint32_t)r * 256u;
        b7[p] = r & 7;
    }

    float acc[2][4][4];
    #pragma unroll
    for (int i = 0; i < 2; i++)
        #pragma unroll
        for (int j = 0; j < 4; j++)
            #pragma unroll
            for (int c = 0; c < 4; c++) acc[i][j][c] = 0.f;

    const int u0  = 4 * (tid & 31);      // A-producer u quad (warp spans all u)
    const int r0p = (tid >> 5) * 8;      // A-producer row group (8 rows, per warp)

    // ---- path loop ---------------------------------------------------------
    #pragma unroll
    for (int pi = 0; pi < NP; pi++) {
        {
            const int l1 = kCfg[LO].l1[pi];
            const int cbase = kCfg[LO].cb[pi];
            if (l1 == 0)
                produceA<1, DL, NC>(x1, ct, smem, m0, r0p, u0, n_lo, Ntot, 0, cbase);
            else if (l1 == 1)
                produceA<3, DL, NC>(x1, ct, smem, m0, r0p, u0, n_lo, Ntot, 128, cbase);
            else
                produceA<5, DL, NC>(x1, ct, smem, m0, r0p, u0, n_lo, Ntot, 512, cbase);
        }

        asm volatile("cp.async.wait_group 0;" ::: "memory");
        __syncthreads();   // A(pi) + B(pi) ready for all warps

        // ---- MMA(pi): 8 k-steps, single term ------------------------------
        #pragma unroll 1
        for (int ks = 0; ks < 8; ks++) {
            const int ch = 2 * ks + khalf;
            uint32_t ah[2][4], bh[2][4];
            #pragma unroll
            for (int mt = 0; mt < 2; mt++)
                LDSM4(ah[mt], sb + AH_OFF + aRow[mt] + (uint32_t)((ch ^ a7[mt]) << 4));
            #pragma unroll
            for (int p = 0; p < 2; p++)
                LDSM4(bh[p], sb + B_OFF + bRow[p] + (uint32_t)((ch ^ b7[p]) << 4));
            #pragma unroll
            for (int mt = 0; mt < 2; mt++)
                #pragma unroll
                for (int p = 0; p < 2; p++) {
                    MMA(acc[mt][2*p],   ah[mt], bh[p][0], bh[p][2]);
                    MMA(acc[mt][2*p+1], ah[mt], bh[p][1], bh[p][3]);
                }
        }

        __syncthreads();   // all warps done reading A(pi), B(pi)

        if (pi + 1 < NP) {  // refill B for next path (overlaps next produce)
            const int gid2 = kCfg[LO].gid[pi + 1];
            for (int c = tid; c < 2048; c += 256)
                cpasync16(sb + B_OFF + c * 16, (const char*)g_B[gid2] + c * 16);
            asm volatile("cp.async.commit_group;" ::: "memory");
        }
    }

    // ---- epilogue: acc -> smem [w][r] transpose -> coalesced stores --------
    float* sepi = (float*)(smem + EPI_OFF);
    {
        const int arow = lane >> 2;
        const int acol = (lane & 3) * 2;
        #pragma unroll
        for (int mt = 0; mt < 2; mt++)
            #pragma unroll
            for (int nt = 0; nt < 4; nt++)
                #pragma unroll
                for (int c = 0; c < 4; c++) {
                    int r = mrow0 + mt * 16 + arow + ((c >> 1) << 3);
                    int w = ncol0 + nt * 8 + acol + (c & 1);
                    sepi[w * 68 + r] = acc[mt][nt][c];
                }
    }
    __syncthreads();

    constexpr int WDL = 128 * DL;
    const int tot = n_count * WDL;
    for (int e = tid; e < tot; e += 256) {
        int ni = e / WDL, o = e - ni * WDL;    // compile-time divisors
        int wq = o / DL, k = o - wq * DL;
        int n = n_lo + ni;
        int r = n * DL + k - m0;
        if (n < Ntot && r >= 0 && r < 64)
            out[(size_t)n * 1152 + OB + o] = sepi[wq * 68 + r];
    }
}

// ============================================================================
// fused GEMM kernel: dispatch on lo, then fully-templated body
// ============================================================================
__global__ __launch_bounds__(256, 4)
void fctp_gemm(const float* __restrict__ x1, const float* __restrict__ x2,
               float* __restrict__ out, int Ntot, int T0, int T1,
               const __grid_constant__ Params P)
{
    extern __shared__ char smem[];
    const int b = blockIdx.x;
    if (b < T0)           body<0>(b,            x1, x2, out, Ntot, P, smem);
    else if (b < T0 + T1) body<1>(b - T0,       x1, x2, out, Ntot, P, smem);
    else                  body<2>(b - T0 - T1,  x1, x2, out, Ntot, P, smem);
}

// ============================================================================
// Host: Wigner-3j construction (fp64, identical math to the reference)
// ============================================================================
typedef std::complex<double> cd;

static double factd(int n) { double r = 1; for (int i = 2; i <= n; i++) r *= i; return r; }

static double su2cg(int j1, int m1, int j2, int m2, int j3, int m3) {
    if (m3 != m1 + m2) return 0.0;
    int vmin = -j1 + j2 + m3; if (-j1 + m1 > vmin) vmin = -j1 + m1; if (0 > vmin) vmin = 0;
    int vmax = j2 + j3 + m1; if (j3 - j1 + j2 < vmax) vmax = j3 - j1 + j2; if (j3 + m3 < vmax) vmax = j3 + m3;
    if (vmax < vmin) return 0.0;
    double pref = (2.0 * j3 + 1.0) *
        (factd(j3 + j1 - j2) * factd(j3 - j1 + j2) * factd(j1 + j2 - j3) *
         factd(j3 + m3) * factd(j3 - m3)) /
        (factd(j1 + j2 + j3 + 1) * factd(j1 - m1) * factd(j1 + m1) *
         factd(j2 - m2) * factd(j2 + m2));
    double S = 0.0;
    for (int v = vmin; v <= vmax; v++) {
        int par = v + j2 + m2;
        double sgn = (((par % 2) + 2) % 2) ? -1.0 : 1.0;
        S += sgn * (factd(j2 + j3 + m1 - v) * factd(j1 - m1 + v)) /
             (factd(v) * factd(j3 - j1 + j2 - v) * factd(j3 + m3 - v) *
              factd(v + j1 - j2 - m3));
    }
    return sqrt(pref) * S;
}

static void calcq(int l, cd q[5][5]) {
    for (int a = 0; a < 5; a++) for (int b = 0; b < 5; b++) q[a][b] = cd(0, 0);
    const double s2 = 1.0 / sqrt(2.0);
    for (int m = -l; m < 0; m++) {
        q[l + m][l - m] = cd(s2, 0);
        q[l + m][l + m] = cd(0, -s2);
    }
    q[l][l] = cd(1, 0);
    for (int m = 1; m <= l; m++) {
        double sg = (m % 2) ? -1.0 : 1.0;
        q[l + m][l + m] = cd(sg * s2, 0);
        q[l + m][l - m] = cd(0, sg * s2);
    }
    cd f = (l == 0) ? cd(1, 0) : (l == 1) ? cd(0, -1) : cd(-1, 0); // (-i)^l
    for (int a = 0; a < 5; a++) for (int b = 0; b < 5; b++) q[a][b] *= f;
}

static void calc_w3j(int l1, int l2, int l3, double* outv) {
    int d1 = 2 * l1 + 1, d2 = 2 * l2 + 1, d3 = 2 * l3 + 1;
    double C[5][5][5];
    memset(C, 0, sizeof(C));
    for (int m1 = -l1; m1 <= l1; m1++)
        for (int m2 = -l2; m2 <= l2; m2++) {
            int m3 = m1 + m2;
            if (m3 >= -l3 && m3 <= l3)
                C[m1 + l1][m2 + l2][m3 + l3] = su2cg(l1, m1, l2, m2, l3, m3);
        }
    cd Q1[5][5], Q2[5][5], Q3[5][5];
    calcq(l1, Q1); calcq(l2, Q2); calcq(l3, Q3);
    static cd Cc[5][5][5];
    for (int j = 0; j < d1; j++)
        for (int l = 0; l < d2; l++)
            for (int m = 0; m < d3; m++) {
                cd s(0, 0);
                for (int i = 0; i < d1; i++)
                    for (int k = 0; k < d2; k++)
                        for (int n = 0; n < d3; n++)
                            s += Q1[i][j] * Q2[k][l] * std::conj(Q3[n][m]) * C[i][k][n];
                Cc[j][l][m] = s;
            }
    double nr = 0, ni = 0;
    for (int j = 0; j < d1; j++)
        for (int l = 0; l < d2; l++)
            for (int m = 0; m < d3; m++) {
                nr += Cc[j][l][m].real() * Cc[j][l][m].real();
                ni += Cc[j][l][m].imag() * Cc[j][l][m].imag();
            }
    bool useR = sqrt(nr) >= sqrt(ni);
    double nrm = sqrt(useR ? nr : ni);
    for (int j = 0; j < d1; j++)
        for (int l = 0; l < d2; l++)
            for (int m = 0; m < d3; m++)
                outv[(j * d2 + l) * d3 + m] =
                    (useR ? Cc[j][l][m].real() : Cc[j][l][m].imag()) / nrm;
}

static void build_params(Params& P) {
    static const int L1[NPATHS]   = {0,0,0,1,1,1,1,2,2,2,2};
    static const int L2[NPATHS]   = {0,1,2,0,1,1,2,0,1,2,2};
    static const int LOA[NPATHS]  = {0,1,2,1,0,2,1,2,1,0,2};
    static const int cof3[NPATHS] = {0,1,10,35,44,53,98,143,168,213,238};
    static const int x2off[3] = {0, 1, 4};
    const double pw[3] = { sqrt(1.0/384.0), sqrt(3.0/512.0), sqrt(5.0/512.0) };

    for (int p = 0; p < NPATHS; p++) {
        int d1 = 2*L1[p] + 1, d2 = 2*L2[p] + 1, d3 = 2*LOA[p] + 1;
        double buf[125];
        calc_w3j(L1[p], L2[p], LOA[p], buf);
        for (int idx = 0; idx < d1*d2*d3; idx++)
            P.C[cof3[p] + idx] = (float)(buf[idx] * pw[LOA[p]]);
    }
    int ci = 0;
    for (int lo = 0; lo < 3; lo++) {
        P.cmap_off[lo] = ci;
        int d3 = 2*lo + 1;
        for (int gid = 0; gid < NPATHS; gid++) {
            if (LOA[gid] != lo) continue;
            int d1 = 2*L1[gid] + 1, d2 = 2*L2[gid] + 1;
            for (int i = 0; i < d1; i++)
                for (int k = 0; k < d3; k++)
                    P.cmap[ci++] = make_int4(cof3[gid] + i*d2*d3 + k, d2, d3,
                                             x2off[L2[gid]]);
        }
    }
}

extern "C" void kernel_launch(void* const* d_in, const int* in_sizes, int n_in,
                              void* d_out, int out_size)
{
    const float* x1  = (const float*)d_in[0];
    const float* x2  = (const float*)d_in[1];
    const float* wt  = (const float*)d_in[2];
    float*       out = (float*)d_out;
    const int N = in_sizes[0] / 1152;

    Params P;
    build_params(P);

    cudaFuncSetAttribute(fctp_gemm,
                         cudaFuncAttributeMaxDynamicSharedMemorySize, SMEM_TOTAL);

    wprep_kernel<<<NPATHS, 256>>>(wt);

    const int T0 = (N     + 63) / 64;
    const int T1 = (3 * N + 63) / 64;
    const int T2 = (5 * N + 63) / 64;
    fctp_gemm<<<T0 + T1 + T2, 256, SMEM_TOTAL>>>(x1, x2, out, N, T0, T1, P);
}

// round 14
// speedup vs baseline: 1.1518x; 1.0533x over previous
#include <cuda_runtime.h>
#include <cuda_fp16.h>
#include <math.h>
#include <complex>
#include <cstring>
#include <cstdint>

// ============================================================================
// FullyConnectedTensorProduct, two-kernel scheme (R13):
//   aprep: per-n streaming kernel computes A_p[n,u,k] fp16 for ALL paths,
//          written pre-swizzled in 64x128 GEMM tile format (g_A, 183 MB).
//          Reads each x1 row once.
//   fctp_gemm: pure cp.async-pipelined mma.sync GEMM; per (lo, mt) CTA loops
//          paths, double-buffering A (16KB, DRAM) + B (32KB, L2) stages.
//   Single fp16 term Ah*Wh (rel ~2.9e-4 vs 1e-3 threshold), math order
//   identical to the R12 fused kernel -> bit-identical output.
// ============================================================================

#define NPATHS 11

// ---- A scratch: tiles of 64 rows x 128 u fp16 (8192 halves, swizzled) ------
// capacity for N_MAX=20480: lo0 3x320, lo1 4x960, lo2 4x1600 = 11200 tiles
#define AT_LO0   0
#define AT_LO1   960
#define AT_LO2   4800
#define AT_TOT   11200
__device__ __align__(16) __half g_A[(size_t)AT_TOT * 8192];
__device__ __align__(16) __half g_B[NPATHS][16384];   // weights, fp16 hi

// ---- GEMM smem layout (bytes): A double-buf + B double-buf -----------------
#define A0_OFF    0
#define A1_OFF    16384
#define B0_OFF    32768
#define B1_OFF    65536
#define SMEM_TOTAL 98304
#define EPI_OFF   0          // epilogue transpose buffer reuses stage region

struct Params {
    float C[363];       // w3j tensors, scaled by PW[lo]
    int4  cmap[115];    // {Cstart, nj, jstride, x2off}, ALL-paths order p0..p10
};

// per-lo GEMM path tables: B weight ids (slot order matches aprep tile bases)
struct LoCfg { int np; int gid[4]; };
__device__ __constant__ const LoCfg kCfg[3] = {
    {3, {0,4,9,0}},
    {4, {1,3,6,8}},
    {4, {2,5,7,10}},
};

// ---- PTX helpers -----------------------------------------------------------
__device__ __forceinline__ uint32_t smem_u32(const void* p) {
    uint32_t a;
    asm("{ .reg .u64 t; cvta.to.shared.u64 t, %1; cvt.u32.u64 %0, t; }"
        : "=r"(a) : "l"(p));
    return a;
}
__device__ __forceinline__ void cpasync16(uint32_t dst, const void* src) {
    asm volatile("cp.async.cg.shared.global [%0], [%1], 16;"
                 :: "r"(dst), "l"(src) : "memory");
}
#define LDSM4(R, ADDR)                                                        \
    asm volatile("ldmatrix.sync.aligned.m8n8.x4.shared.b16 "                  \
                 "{%0,%1,%2,%3}, [%4];"                                       \
                 : "=r"((R)[0]), "=r"((R)[1]), "=r"((R)[2]), "=r"((R)[3])     \
                 : "r"(ADDR))
#define MMA(D, A, B0, B1)                                                     \
    asm volatile("mma.sync.aligned.m16n8k16.row.col.f32.f16.f16.f32 "         \
                 "{%0,%1,%2,%3}, {%4,%5,%6,%7}, {%8,%9}, {%0,%1,%2,%3};"      \
                 : "+f"((D)[0]), "+f"((D)[1]), "+f"((D)[2]), "+f"((D)[3])     \
                 : "r"((A)[0]), "r"((A)[1]), "r"((A)[2]), "r"((A)[3]),        \
                   "r"(B0), "r"(B1))

// swizzled byte offset of (row, half-col u) in a [rows]x128 fp16 tile
__device__ __host__ __forceinline__ uint32_t swz(int row, int u) {
    return (uint32_t)row * 256u
         + (uint32_t)(((u >> 3) ^ (row & 7)) << 4)
         + (uint32_t)((u & 7) * 2);
}

// ============================================================================
// wprep: weights -> fp16, transposed [w][u], pre-swizzled tiles
// ============================================================================
__global__ void wprep_kernel(const float* __restrict__ wt) {
    const int gid = blockIdx.x;
    const float* wp = wt + (size_t)gid * 16384;
    for (int idx = threadIdx.x; idx < 16384; idx += blockDim.x) {
        int u = idx >> 7, w = idx & 127;
        g_B[gid][swz(w, u) >> 1] = __float2half_rn(wp[u * 128 + w]);
    }
}

// ============================================================================
// aprep: per-n A materialization. Block = 8 n's x 256 threads.
// Thread (nl = tid>>5, q = tid&31) handles u quad u0 = 4q for its n.
// Writes uint2 (4 fp16) per (path, k) into the swizzled tile position.
// ============================================================================
#define PREP_PATH(CB, D1, DLP, TB, XS) {                                      \
    const int mbase = n * (DLP);                                              \
    _Pragma("unroll")                                                         \
    for (int k = 0; k < (DLP); k++) {                                         \
        float s0 = 0.f, s1 = 0.f, s2 = 0.f, s3 = 0.f;                         \
        _Pragma("unroll")                                                     \
        for (int i = 0; i < (D1); i++) {                                      \
            float cc = cn[(CB) + i * (DLP) + k];                              \
            s0 += XS[0 * (D1) + i] * cc;                                      \
            s1 += XS[1 * (D1) + i] * cc;                                      \
            s2 += XS[2 * (D1) + i] * cc;                                      \
            s3 += XS[3 * (D1) + i] * cc;                                      \
        }                                                                     \
        __half2 pa = __floats2half2_rn(s0, s1);                               \
        __half2 pb = __floats2half2_rn(s2, s3);                               \
        int mm = mbase + k;                                                   \
        int tt = mm >> 6, r = mm & 63;                                        \
        *(uint2*)((char*)g_A + ((size_t)((TB) + tt) << 14) + swz(r, u0)) =    \
            make_uint2(*(uint32_t*)&pa, *(uint32_t*)&pb);                     \
    } }

__global__ __launch_bounds__(256)
void aprep_kernel(const float* __restrict__ x1, const float* __restrict__ x2,
                  int Ntot, const __grid_constant__ Params P)
{
    __shared__ float ct[8][116];
    const int tid = threadIdx.x;
    const int n0 = blockIdx.x * 8;

    // c-table for the 8 n's (ALL-paths order, 115 entries per n)
    for (int t = tid; t < 8 * 115; t += 256) {
        int nl = t / 115, e = t - nl * 115;
        int n = n0 + nl;
        float s = 0.f;
        if (n < Ntot) {
            int4 m = P.cmap[e];
            const float* xr = x2 + (size_t)n * 9 + m.w;
            for (int j = 0; j < m.y; j++) s += P.C[m.x + j * m.z] * xr[j];
        }
        ct[nl][e] = s;
    }
    __syncthreads();

    const int nl = tid >> 5, q = tid & 31;
    const int n = n0 + nl;
    if (n >= Ntot) return;
    const int u0 = 4 * q;

    // x1 row segments for 4 u's, vectorized
    const float* xr = x1 + (size_t)n * 1152;
    float x0v[4], x1v[12], x2v[20];
    *(float4*)x0v = *(const float4*)(xr + u0);
    #pragma unroll
    for (int i = 0; i < 3; i++)
        *(float4*)(x1v + 4 * i) = *(const float4*)(xr + 128 + 12 * q + 4 * i);
    #pragma unroll
    for (int i = 0; i < 5; i++)
        *(float4*)(x2v + 4 * i) = *(const float4*)(xr + 512 + 20 * q + 4 * i);

    const float* cn = ct[nl];
    PREP_PATH( 0, 1, 1, AT_LO0 +    0, x0v)   // p0  (0,0,0)
    PREP_PATH( 1, 1, 3, AT_LO1 +    0, x0v)   // p1  (0,1,1)
    PREP_PATH( 4, 1, 5, AT_LO2 +    0, x0v)   // p2  (0,2,2)
    PREP_PATH( 9, 3, 3, AT_LO1 +  960, x1v)   // p3  (1,0,1)
    PREP_PATH(18, 3, 1, AT_LO0 +  320, x1v)   // p4  (1,1,0)
    PREP_PATH(21, 3, 5, AT_LO2 + 1600, x1v)   // p5  (1,1,2)
    PREP_PATH(36, 3, 3, AT_LO1 + 1920, x1v)   // p6  (1,2,1)
    PREP_PATH(45, 5, 5, AT_LO2 + 3200, x2v)   // p7  (2,0,2)
    PREP_PATH(70, 5, 3, AT_LO1 + 2880, x2v)   // p8  (2,1,1)
    PREP_PATH(85, 5, 1, AT_LO0 +  640, x2v)   // p9  (2,2,0)
    PREP_PATH(90, 5, 5, AT_LO2 + 4800, x2v)   // p10 (2,2,2)
}

// ============================================================================
// GEMM body: pure cp.async pipeline, templated on LO
// ============================================================================
template<int LO>
__device__ __forceinline__ void body(
    int mt_idx, float* __restrict__ out, int Ntot, char* smem)
{
    constexpr int DL  = 2 * LO + 1;
    constexpr int NP  = (LO == 0) ? 3 : 4;
    constexpr int OB  = (LO == 0) ? 0 : (LO == 1) ? 128 : 512;
    constexpr int ATB = (LO == 0) ? AT_LO0 : (LO == 1) ? AT_LO1 : AT_LO2;
    constexpr int ATS = (LO == 0) ? 320 : (LO == 1) ? 960 : 1600;

    const uint32_t sb = smem_u32(smem);
    const int tid  = threadIdx.x;
    const int wid  = tid >> 5;
    const int lane = tid & 31;

    const int m0 = mt_idx * 64;
    const int n_lo = m0 / DL;
    int n_hi = (m0 + 63) / DL;
    if (n_hi > Ntot - 1) n_hi = Ntot - 1;
    const int n_count = n_hi - n_lo + 1;

    // stage loader: A tile (16KB) + B tile (32KB) -> buf, one commit group
    auto loadStage = [&](int pi, int buf) {
        const char* asrc = (const char*)g_A
                         + ((size_t)(ATB + pi * ATS + mt_idx) << 14);
        uint32_t ad = sb + (buf ? A1_OFF : A0_OFF);
        for (int c = tid; c < 1024; c += 256)
            cpasync16(ad + c * 16, asrc + c * 16);
        const int gid = kCfg[LO].gid[pi];
        uint32_t bd = sb + (buf ? B1_OFF : B0_OFF);
        for (int c = tid; c < 2048; c += 256)
            cpasync16(bd + c * 16, (const char*)g_B[gid] + c * 16);
        asm volatile("cp.async.commit_group;" ::: "memory");
    };
    loadStage(0, 0);

    // warp tiling: 2x4 grid, warp = 32M x 32N
    const int mrow0 = (wid >> 2) * 32;
    const int ncol0 = (wid & 3) * 32;
    const int lrow  = lane & 15;
    const int khalf = lane >> 4;

    uint32_t aRow[2]; int a7[2];
    #pragma unroll
    for (int mt = 0; mt < 2; mt++) {
        int r = mrow0 + mt * 16 + lrow;
        aRow[mt] = (uint32_t)r * 256u;
        a7[mt] = r & 7;
    }
    uint32_t bRow[2]; int b7[2];
    #pragma unroll
    for (int p = 0; p < 2; p++) {
        int r = ncol0 + p * 16 + lrow;
        bRow[p] = (uint32_t)r * 256u;
        b7[p] = r & 7;
    }

    float acc[2][4][4];
    #pragma unroll
    for (int i = 0; i < 2; i++)
        #pragma unroll
        for (int j = 0; j < 4; j++)
            #pragma unroll
            for (int c = 0; c < 4; c++) acc[i][j][c] = 0.f;

    // ---- path loop: wait -> sync -> issue next -> MMA ----------------------
    #pragma unroll
    for (int pi = 0; pi < NP; pi++) {
        asm volatile("cp.async.wait_group 0;" ::: "memory");
        __syncthreads();      // loads(pi) visible; all warps past MMA(pi-1)
        if (pi + 1 < NP) loadStage(pi + 1, (pi + 1) & 1);

        const uint32_t abase = sb + ((pi & 1) ? A1_OFF : A0_OFF);
        const uint32_t bbase = sb + ((pi & 1) ? B1_OFF : B0_OFF);
        #pragma unroll 1
        for (int ks = 0; ks < 8; ks++) {
            const int ch = 2 * ks + khalf;
            uint32_t ah[2][4], bh[2][4];
            #pragma unroll
            for (int mt = 0; mt < 2; mt++)
                LDSM4(ah[mt], abase + aRow[mt] + (uint32_t)((ch ^ a7[mt]) << 4));
            #pragma unroll
            for (int p = 0; p < 2; p++)
                LDSM4(bh[p], bbase + bRow[p] + (uint32_t)((ch ^ b7[p]) << 4));
            #pragma unroll
            for (int mt = 0; mt < 2; mt++)
                #pragma unroll
                for (int p = 0; p < 2; p++) {
                    MMA(acc[mt][2*p],   ah[mt], bh[p][0], bh[p][2]);
                    MMA(acc[mt][2*p+1], ah[mt], bh[p][1], bh[p][3]);
                }
        }
    }

    // ---- epilogue: acc -> smem [w][r] transpose -> coalesced stores --------
    __syncthreads();          // all warps done with last stage before reuse
    float* sepi = (float*)(smem + EPI_OFF);
    {
        const int arow = lane >> 2;
        const int acol = (lane & 3) * 2;
        #pragma unroll
        for (int mt = 0; mt < 2; mt++)
            #pragma unroll
            for (int nt = 0; nt < 4; nt++)
                #pragma unroll
                for (int c = 0; c < 4; c++) {
                    int r = mrow0 + mt * 16 + arow + ((c >> 1) << 3);
                    int w = ncol0 + nt * 8 + acol + (c & 1);
                    sepi[w * 68 + r] = acc[mt][nt][c];
                }
    }
    __syncthreads();

    constexpr int WDL = 128 * DL;
    const int tot = n_count * WDL;
    for (int e = tid; e < tot; e += 256) {
        int ni = e / WDL, o = e - ni * WDL;    // compile-time divisors
        int wq = o / DL, k = o - wq * DL;
        int n = n_lo + ni;
        int r = n * DL + k - m0;
        if (n < Ntot && r >= 0 && r < 64)
            out[(size_t)n * 1152 + OB + o] = sepi[wq * 68 + r];
    }
}

__global__ __launch_bounds__(256, 2)
void fctp_gemm(float* __restrict__ out, int Ntot, int T0, int T1)
{
    extern __shared__ char smem[];
    const int b = blockIdx.x;
    if (b < T0)           body<0>(b,           out, Ntot, smem);
    else if (b < T0 + T1) body<1>(b - T0,      out, Ntot, smem);
    else                  body<2>(b - T0 - T1, out, Ntot, smem);
}

// ============================================================================
// Host: Wigner-3j construction (fp64, identical math to the reference)
// ============================================================================
typedef std::complex<double> cd;

static double factd(int n) { double r = 1; for (int i = 2; i <= n; i++) r *= i; return r; }

static double su2cg(int j1, int m1, int j2, int m2, int j3, int m3) {
    if (m3 != m1 + m2) return 0.0;
    int vmin = -j1 + j2 + m3; if (-j1 + m1 > vmin) vmin = -j1 + m1; if (0 > vmin) vmin = 0;
    int vmax = j2 + j3 + m1; if (j3 - j1 + j2 < vmax) vmax = j3 - j1 + j2; if (j3 + m3 < vmax) vmax = j3 + m3;
    if (vmax < vmin) return 0.0;
    double pref = (2.0 * j3 + 1.0) *
        (factd(j3 + j1 - j2) * factd(j3 - j1 + j2) * factd(j1 + j2 - j3) *
         factd(j3 + m3) * factd(j3 - m3)) /
        (factd(j1 + j2 + j3 + 1) * factd(j1 - m1) * factd(j1 + m1) *
         factd(j2 - m2) * factd(j2 + m2));
    double S = 0.0;
    for (int v = vmin; v <= vmax; v++) {
        int par = v + j2 + m2;
        double sgn = (((par % 2) + 2) % 2) ? -1.0 : 1.0;
        S += sgn * (factd(j2 + j3 + m1 - v) * factd(j1 - m1 + v)) /
             (factd(v) * factd(j3 - j1 + j2 - v) * factd(j3 + m3 - v) *
              factd(v + j1 - j2 - m3));
    }
    return sqrt(pref) * S;
}

static void calcq(int l, cd q[5][5]) {
    for (int a = 0; a < 5; a++) for (int b = 0; b < 5; b++) q[a][b] = cd(0, 0);
    const double s2 = 1.0 / sqrt(2.0);
    for (int m = -l; m < 0; m++) {
        q[l + m][l - m] = cd(s2, 0);
        q[l + m][l + m] = cd(0, -s2);
    }
    q[l][l] = cd(1, 0);
    for (int m = 1; m <= l; m++) {
        double sg = (m % 2) ? -1.0 : 1.0;
        q[l + m][l + m] = cd(sg * s2, 0);
        q[l + m][l - m] = cd(0, sg * s2);
    }
    cd f = (l == 0) ? cd(1, 0) : (l == 1) ? cd(0, -1) : cd(-1, 0); // (-i)^l
    for (int a = 0; a < 5; a++) for (int b = 0; b < 5; b++) q[a][b] *= f;
}

static void calc_w3j(int l1, int l2, int l3, double* outv) {
    int d1 = 2 * l1 + 1, d2 = 2 * l2 + 1, d3 = 2 * l3 + 1;
    double C[5][5][5];
    memset(C, 0, sizeof(C));
    for (int m1 = -l1; m1 <= l1; m1++)
        for (int m2 = -l2; m2 <= l2; m2++) {
            int m3 = m1 + m2;
            if (m3 >= -l3 && m3 <= l3)
                C[m1 + l1][m2 + l2][m3 + l3] = su2cg(l1, m1, l2, m2, l3, m3);
        }
    cd Q1[5][5], Q2[5][5], Q3[5][5];
    calcq(l1, Q1); calcq(l2, Q2); calcq(l3, Q3);
    static cd Cc[5][5][5];
    for (int j = 0; j < d1; j++)
        for (int l = 0; l < d2; l++)
            for (int m = 0; m < d3; m++) {
                cd s(0, 0);
                for (int i = 0; i < d1; i++)
                    for (int k = 0; k < d2; k++)
                        for (int n = 0; n < d3; n++)
                            s += Q1[i][j] * Q2[k][l] * std::conj(Q3[n][m]) * C[i][k][n];
                Cc[j][l][m] = s;
            }
    double nr = 0, ni = 0;
    for (int j = 0; j < d1; j++)
        for (int l = 0; l < d2; l++)
            for (int m = 0; m < d3; m++) {
                nr += Cc[j][l][m].real() * Cc[j][l][m].real();
                ni += Cc[j][l][m].imag() * Cc[j][l][m].imag();
            }
    bool useR = sqrt(nr) >= sqrt(ni);
    double nrm = sqrt(useR ? nr : ni);
    for (int j = 0; j < d1; j++)
        for (int l = 0; l < d2; l++)
            for (int m = 0; m < d3; m++)
                outv[(j * d2 + l) * d3 + m] =
                    (useR ? Cc[j][l][m].real() : Cc[j][l][m].imag()) / nrm;
}

static void build_params(Params& P) {
    static const int L1[NPATHS]   = {0,0,0,1,1,1,1,2,2,2,2};
    static const int L2[NPATHS]   = {0,1,2,0,1,1,2,0,1,2,2};
    static const int LOA[NPATHS]  = {0,1,2,1,0,2,1,2,1,0,2};
    static const int cof3[NPATHS] = {0,1,10,35,44,53,98,143,168,213,238};
    static const int x2off[3] = {0, 1, 4};
    const double pw[3] = { sqrt(1.0/384.0), sqrt(3.0/512.0), sqrt(5.0/512.0) };

    for (int p = 0; p < NPATHS; p++) {
        int d1 = 2*L1[p] + 1, d2 = 2*L2[p] + 1, d3 = 2*LOA[p] + 1;
        double buf[125];
        calc_w3j(L1[p], L2[p], LOA[p], buf);
        for (int idx = 0; idx < d1*d2*d3; idx++)
            P.C[cof3[p] + idx] = (float)(buf[idx] * pw[LOA[p]]);
    }
    // cmap in ALL-paths order p0..p10 (i-major, k-minor) -> cbases
    // {0,1,4,9,18,21,36,45,70,85,90}
    int ci = 0;
    for (int p = 0; p < NPATHS; p++) {
        int d1 = 2*L1[p] + 1, d2 = 2*L2[p] + 1, d3 = 2*LOA[p] + 1;
        for (int i = 0; i < d1; i++)
            for (int k = 0; k < d3; k++)
                P.cmap[ci++] = make_int4(cof3[p] + i*d2*d3 + k, d2, d3,
                                         x2off[L2[p]]);
    }
}

extern "C" void kernel_launch(void* const* d_in, const int* in_sizes, int n_in,
                              void* d_out, int out_size)
{
    const float* x1  = (const float*)d_in[0];
    const float* x2  = (const float*)d_in[1];
    const float* wt  = (const float*)d_in[2];
    float*       out = (float*)d_out;
    const int N = in_sizes[0] / 1152;

    Params P;
    build_params(P);

    cudaFuncSetAttribute(fctp_gemm,
                         cudaFuncAttributeMaxDynamicSharedMemorySize, SMEM_TOTAL);

    wprep_kernel<<<NPATHS, 256>>>(wt);
    aprep_kernel<<<(N + 7) / 8, 256>>>(x1, x2, N, P);

    const int T0 = (N     + 63) / 64;
    const int T1 = (3 * N + 63) / 64;
    const int T2 = (5 * N + 63) / 64;
    fctp_gemm<<<T0 + T1 + T2, 256, SMEM_TOTAL>>>(out, N, T0, T1);
}

// round 15
// speedup vs baseline: 1.2522x; 1.0872x over previous
#include <cuda_runtime.h>
#include <cuda_fp16.h>
#include <math.h>
#include <complex>
#include <cstring>
#include <cstdint>

// ============================================================================
// FullyConnectedTensorProduct, two-launch scheme (R14):
//   prep (fused): blocks [0, NA) run aprep (A materialization, fp16, swizzled
//        64x128 tiles in g_A); blocks [NA, NA+44) run wprep (weights->fp16
//        transposed/swizzled in g_B). Independent work, one launch -> the
//        22.9us serial wprep stage from R13 disappears into aprep's shadow.
//   fctp_gemm: pure cp.async-pipelined mma.sync GEMM (unchanged from R13).
//   Single fp16 term Ah*Wh; output bit-identical to R12/R13 (rel ~2.94e-4).
// ============================================================================

#define NPATHS 11

// ---- A scratch: tiles of 64 rows x 128 u fp16 (8192 halves, swizzled) ------
#define AT_LO0   0
#define AT_LO1   960
#define AT_LO2   4800
#define AT_TOT   11200
__device__ __align__(16) __half g_A[(size_t)AT_TOT * 8192];
__device__ __align__(16) __half g_B[NPATHS][16384];   // weights, fp16 hi

// ---- GEMM smem layout (bytes): A double-buf + B double-buf -----------------
#define A0_OFF    0
#define A1_OFF    16384
#define B0_OFF    32768
#define B1_OFF    65536
#define SMEM_TOTAL 98304
#define EPI_OFF   0          // epilogue transpose buffer reuses stage region

#define WPREP_BLOCKS 44      // 11 paths * 16384 elems / 4096 per block

struct Params {
    float C[363];       // w3j tensors, scaled by PW[lo]
    int4  cmap[115];    // {Cstart, nj, jstride, x2off}, ALL-paths order p0..p10
};

// per-lo GEMM path tables: B weight ids (slot order matches aprep tile bases)
struct LoCfg { int np; int gid[4]; };
__device__ __constant__ const LoCfg kCfg[3] = {
    {3, {0,4,9,0}},
    {4, {1,3,6,8}},
    {4, {2,5,7,10}},
};

// ---- PTX helpers -----------------------------------------------------------
__device__ __forceinline__ uint32_t smem_u32(const void* p) {
    uint32_t a;
    asm("{ .reg .u64 t; cvta.to.shared.u64 t, %1; cvt.u32.u64 %0, t; }"
        : "=r"(a) : "l"(p));
    return a;
}
__device__ __forceinline__ void cpasync16(uint32_t dst, const void* src) {
    asm volatile("cp.async.cg.shared.global [%0], [%1], 16;"
                 :: "r"(dst), "l"(src) : "memory");
}
#define LDSM4(R, ADDR)                                                        \
    asm volatile("ldmatrix.sync.aligned.m8n8.x4.shared.b16 "                  \
                 "{%0,%1,%2,%3}, [%4];"                                       \
                 : "=r"((R)[0]), "=r"((R)[1]), "=r"((R)[2]), "=r"((R)[3])     \
                 : "r"(ADDR))
#define MMA(D, A, B0, B1)                                                     \
    asm volatile("mma.sync.aligned.m16n8k16.row.col.f32.f16.f16.f32 "         \
                 "{%0,%1,%2,%3}, {%4,%5,%6,%7}, {%8,%9}, {%0,%1,%2,%3};"      \
                 : "+f"((D)[0]), "+f"((D)[1]), "+f"((D)[2]), "+f"((D)[3])     \
                 : "r"((A)[0]), "r"((A)[1]), "r"((A)[2]), "r"((A)[3]),        \
                   "r"(B0), "r"(B1))

// swizzled byte offset of (row, half-col u) in a [rows]x128 fp16 tile
__device__ __host__ __forceinline__ uint32_t swz(int row, int u) {
    return (uint32_t)row * 256u
         + (uint32_t)(((u >> 3) ^ (row & 7)) << 4)
         + (uint32_t)((u & 7) * 2);
}

// ============================================================================
// fused prep kernel: aprep blocks + wprep blocks in one launch
// ============================================================================
#define PREP_PATH(CB, D1, DLP, TB, XS) {                                      \
    const int mbase = n * (DLP);                                              \
    _Pragma("unroll")                                                         \
    for (int k = 0; k < (DLP); k++) {                                         \
        float s0 = 0.f, s1 = 0.f, s2 = 0.f, s3 = 0.f;                         \
        _Pragma("unroll")                                                     \
        for (int i = 0; i < (D1); i++) {                                      \
            float cc = cn[(CB) + i * (DLP) + k];                              \
            s0 += XS[0 * (D1) + i] * cc;                                      \
            s1 += XS[1 * (D1) + i] * cc;                                      \
            s2 += XS[2 * (D1) + i] * cc;                                      \
            s3 += XS[3 * (D1) + i] * cc;                                      \
        }                                                                     \
        __half2 pa = __floats2half2_rn(s0, s1);                               \
        __half2 pb = __floats2half2_rn(s2, s3);                               \
        int mm = mbase + k;                                                   \
        int tt = mm >> 6, r = mm & 63;                                        \
        *(uint2*)((char*)g_A + ((size_t)((TB) + tt) << 14) + swz(r, u0)) =    \
            make_uint2(*(uint32_t*)&pa, *(uint32_t*)&pb);                     \
    } }

__global__ __launch_bounds__(256)
void prep_kernel(const float* __restrict__ x1, const float* __restrict__ x2,
                 const float* __restrict__ wt, int Ntot, int NA,
                 const __grid_constant__ Params P)
{
    const int tid = threadIdx.x;

    if ((int)blockIdx.x >= NA) {
        // ---- wprep part: 4096 weight elements per block --------------------
        const int base = ((int)blockIdx.x - NA) * 4096;
        #pragma unroll
        for (int it = 0; it < 16; it++) {
            int idx = base + it * 256 + tid;          // global weight elem
            int gid = idx >> 14;                       // path
            int e   = idx & 16383;
            int u = e >> 7, w = e & 127;
            g_B[gid][swz(w, u) >> 1] =
                __float2half_rn(wt[(size_t)gid * 16384 + u * 128 + w]);
        }
        return;
    }

    // ---- aprep part: 8 n's per block ---------------------------------------
    __shared__ float ct[8][116];
    const int n0 = (int)blockIdx.x * 8;

    for (int t = tid; t < 8 * 115; t += 256) {
        int nl = t / 115, e = t - nl * 115;
        int n = n0 + nl;
        float s = 0.f;
        if (n < Ntot) {
            int4 m = P.cmap[e];
            const float* xr = x2 + (size_t)n * 9 + m.w;
            for (int j = 0; j < m.y; j++) s += P.C[m.x + j * m.z] * xr[j];
        }
        ct[nl][e] = s;
    }
    __syncthreads();

    const int nl = tid >> 5, q = tid & 31;
    const int n = n0 + nl;
    if (n >= Ntot) return;
    const int u0 = 4 * q;

    const float* xr = x1 + (size_t)n * 1152;
    float x0v[4], x1v[12], x2v[20];
    *(float4*)x0v = *(const float4*)(xr + u0);
    #pragma unroll
    for (int i = 0; i < 3; i++)
        *(float4*)(x1v + 4 * i) = *(const float4*)(xr + 128 + 12 * q + 4 * i);
    #pragma unroll
    for (int i = 0; i < 5; i++)
        *(float4*)(x2v + 4 * i) = *(const float4*)(xr + 512 + 20 * q + 4 * i);

    const float* cn = ct[nl];
    PREP_PATH( 0, 1, 1, AT_LO0 +    0, x0v)   // p0  (0,0,0)
    PREP_PATH( 1, 1, 3, AT_LO1 +    0, x0v)   // p1  (0,1,1)
    PREP_PATH( 4, 1, 5, AT_LO2 +    0, x0v)   // p2  (0,2,2)
    PREP_PATH( 9, 3, 3, AT_LO1 +  960, x1v)   // p3  (1,0,1)
    PREP_PATH(18, 3, 1, AT_LO0 +  320, x1v)   // p4  (1,1,0)
    PREP_PATH(21, 3, 5, AT_LO2 + 1600, x1v)   // p5  (1,1,2)
    PREP_PATH(36, 3, 3, AT_LO1 + 1920, x1v)   // p6  (1,2,1)
    PREP_PATH(45, 5, 5, AT_LO2 + 3200, x2v)   // p7  (2,0,2)
    PREP_PATH(70, 5, 3, AT_LO1 + 2880, x2v)   // p8  (2,1,1)
    PREP_PATH(85, 5, 1, AT_LO0 +  640, x2v)   // p9  (2,2,0)
    PREP_PATH(90, 5, 5, AT_LO2 + 4800, x2v)   // p10 (2,2,2)
}

// ============================================================================
// GEMM body: pure cp.async pipeline, templated on LO (unchanged from R13)
// ============================================================================
template<int LO>
__device__ __forceinline__ void body(
    int mt_idx, float* __restrict__ out, int Ntot, char* smem)
{
    constexpr int DL  = 2 * LO + 1;
    constexpr int NP  = (LO == 0) ? 3 : 4;
    constexpr int OB  = (LO == 0) ? 0 : (LO == 1) ? 128 : 512;
    constexpr int ATB = (LO == 0) ? AT_LO0 : (LO == 1) ? AT_LO1 : AT_LO2;
    constexpr int ATS = (LO == 0) ? 320 : (LO == 1) ? 960 : 1600;

    const uint32_t sb = smem_u32(smem);
    const int tid  = threadIdx.x;
    const int wid  = tid >> 5;
    const int lane = tid & 31;

    const int m0 = mt_idx * 64;
    const int n_lo = m0 / DL;
    int n_hi = (m0 + 63) / DL;
    if (n_hi > Ntot - 1) n_hi = Ntot - 1;
    const int n_count = n_hi - n_lo + 1;

    auto loadStage = [&](int pi, int buf) {
        const char* asrc = (const char*)g_A
                         + ((size_t)(ATB + pi * ATS + mt_idx) << 14);
        uint32_t ad = sb + (buf ? A1_OFF : A0_OFF);
        for (int c = tid; c < 1024; c += 256)
            cpasync16(ad + c * 16, asrc + c * 16);
        const int gid = kCfg[LO].gid[pi];
        uint32_t bd = sb + (buf ? B1_OFF : B0_OFF);
        for (int c = tid; c < 2048; c += 256)
            cpasync16(bd + c * 16, (const char*)g_B[gid] + c * 16);
        asm volatile("cp.async.commit_group;" ::: "memory");
    };
    loadStage(0, 0);

    const int mrow0 = (wid >> 2) * 32;
    const int ncol0 = (wid & 3) * 32;
    const int lrow  = lane & 15;
    const int khalf = lane >> 4;

    uint32_t aRow[2]; int a7[2];
    #pragma unroll
    for (int mt = 0; mt < 2; mt++) {
        int r = mrow0 + mt * 16 + lrow;
        aRow[mt] = (uint32_t)r * 256u;
        a7[mt] = r & 7;
    }
    uint32_t bRow[2]; int b7[2];
    #pragma unroll
    for (int p = 0; p < 2; p++) {
        int r = ncol0 + p * 16 + lrow;
        bRow[p] = (uint32_t)r * 256u;
        b7[p] = r & 7;
    }

    float acc[2][4][4];
    #pragma unroll
    for (int i = 0; i < 2; i++)
        #pragma unroll
        for (int j = 0; j < 4; j++)
            #pragma unroll
            for (int c = 0; c < 4; c++) acc[i][j][c] = 0.f;

    #pragma unroll
    for (int pi = 0; pi < NP; pi++) {
        asm volatile("cp.async.wait_group 0;" ::: "memory");
        __syncthreads();
        if (pi + 1 < NP) loadStage(pi + 1, (pi + 1) & 1);

        const uint32_t abase = sb + ((pi & 1) ? A1_OFF : A0_OFF);
        const uint32_t bbase = sb + ((pi & 1) ? B1_OFF : B0_OFF);
        #pragma unroll 1
        for (int ks = 0; ks < 8; ks++) {
            const int ch = 2 * ks + khalf;
            uint32_t ah[2][4], bh[2][4];
            #pragma unroll
            for (int mt = 0; mt < 2; mt++)
                LDSM4(ah[mt], abase + aRow[mt] + (uint32_t)((ch ^ a7[mt]) << 4));
            #pragma unroll
            for (int p = 0; p < 2; p++)
                LDSM4(bh[p], bbase + bRow[p] + (uint32_t)((ch ^ b7[p]) << 4));
            #pragma unroll
            for (int mt = 0; mt < 2; mt++)
                #pragma unroll
                for (int p = 0; p < 2; p++) {
                    MMA(acc[mt][2*p],   ah[mt], bh[p][0], bh[p][2]);
                    MMA(acc[mt][2*p+1], ah[mt], bh[p][1], bh[p][3]);
                }
        }
    }

    __syncthreads();
    float* sepi = (float*)(smem + EPI_OFF);
    {
        const int arow = lane >> 2;
        const int acol = (lane & 3) * 2;
        #pragma unroll
        for (int mt = 0; mt < 2; mt++)
            #pragma unroll
            for (int nt = 0; nt < 4; nt++)
                #pragma unroll
                for (int c = 0; c < 4; c++) {
                    int r = mrow0 + mt * 16 + arow + ((c >> 1) << 3);
                    int w = ncol0 + nt * 8 + acol + (c & 1);
                    sepi[w * 68 + r] = acc[mt][nt][c];
                }
    }
    __syncthreads();

    constexpr int WDL = 128 * DL;
    const int tot = n_count * WDL;
    for (int e = tid; e < tot; e += 256) {
        int ni = e / WDL, o = e - ni * WDL;
        int wq = o / DL, k = o - wq * DL;
        int n = n_lo + ni;
        int r = n * DL + k - m0;
        if (n < Ntot && r >= 0 && r < 64)
            out[(size_t)n * 1152 + OB + o] = sepi[wq * 68 + r];
    }
}

__global__ __launch_bounds__(256, 2)
void fctp_gemm(float* __restrict__ out, int Ntot, int T0, int T1)
{
    extern __shared__ char smem[];
    const int b = blockIdx.x;
    if (b < T0)           body<0>(b,           out, Ntot, smem);
    else if (b < T0 + T1) body<1>(b - T0,      out, Ntot, smem);
    else                  body<2>(b - T0 - T1, out, Ntot, smem);
}

// ============================================================================
// Host: Wigner-3j construction (fp64, identical math to the reference)
// ============================================================================
typedef std::complex<double> cd;

static double factd(int n) { double r = 1; for (int i = 2; i <= n; i++) r *= i; return r; }

static double su2cg(int j1, int m1, int j2, int m2, int j3, int m3) {
    if (m3 != m1 + m2) return 0.0;
    int vmin = -j1 + j2 + m3; if (-j1 + m1 > vmin) vmin = -j1 + m1; if (0 > vmin) vmin = 0;
    int vmax = j2 + j3 + m1; if (j3 - j1 + j2 < vmax) vmax = j3 - j1 + j2; if (j3 + m3 < vmax) vmax = j3 + m3;
    if (vmax < vmin) return 0.0;
    double pref = (2.0 * j3 + 1.0) *
        (factd(j3 + j1 - j2) * factd(j3 - j1 + j2) * factd(j1 + j2 - j3) *
         factd(j3 + m3) * factd(j3 - m3)) /
        (factd(j1 + j2 + j3 + 1) * factd(j1 - m1) * factd(j1 + m1) *
         factd(j2 - m2) * factd(j2 + m2));
    double S = 0.0;
    for (int v = vmin; v <= vmax; v++) {
        int par = v + j2 + m2;
        double sgn = (((par % 2) + 2) % 2) ? -1.0 : 1.0;
        S += sgn * (factd(j2 + j3 + m1 - v) * factd(j1 - m1 + v)) /
             (factd(v) * factd(j3 - j1 + j2 - v) * factd(j3 + m3 - v) *
              factd(v + j1 - j2 - m3));
    }
    return sqrt(pref) * S;
}

static void calcq(int l, cd q[5][5]) {
    for (int a = 0; a < 5; a++) for (int b = 0; b < 5; b++) q[a][b] = cd(0, 0);
    const double s2 = 1.0 / sqrt(2.0);
    for (int m = -l; m < 0; m++) {
        q[l + m][l - m] = cd(s2, 0);
        q[l + m][l + m] = cd(0, -s2);
    }
    q[l][l] = cd(1, 0);
    for (int m = 1; m <= l; m++) {
        double sg = (m % 2) ? -1.0 : 1.0;
        q[l + m][l + m] = cd(sg * s2, 0);
        q[l + m][l - m] = cd(0, sg * s2);
    }
    cd f = (l == 0) ? cd(1, 0) : (l == 1) ? cd(0, -1) : cd(-1, 0); // (-i)^l
    for (int a = 0; a < 5; a++) for (int b = 0; b < 5; b++) q[a][b] *= f;
}

static void calc_w3j(int l1, int l2, int l3, double* outv) {
    int d1 = 2 * l1 + 1, d2 = 2 * l2 + 1, d3 = 2 * l3 + 1;
    double C[5][5][5];
    memset(C, 0, sizeof(C));
    for (int m1 = -l1; m1 <= l1; m1++)
        for (int m2 = -l2; m2 <= l2; m2++) {
            int m3 = m1 + m2;
            if (m3 >= -l3 && m3 <= l3)
                C[m1 + l1][m2 + l2][m3 + l3] = su2cg(l1, m1, l2, m2, l3, m3);
        }
    cd Q1[5][5], Q2[5][5], Q3[5][5];
    calcq(l1, Q1); calcq(l2, Q2); calcq(l3, Q3);
    static cd Cc[5][5][5];
    for (int j = 0; j < d1; j++)
        for (int l = 0; l < d2; l++)
            for (int m = 0; m < d3; m++) {
                cd s(0, 0);
                for (int i = 0; i < d1; i++)
                    for (int k = 0; k < d2; k++)
                        for (int n = 0; n < d3; n++)
                            s += Q1[i][j] * Q2[k][l] * std::conj(Q3[n][m]) * C[i][k][n];
                Cc[j][l][m] = s;
            }
    double nr = 0, ni = 0;
    for (int j = 0; j < d1; j++)
        for (int l = 0; l < d2; l++)
            for (int m = 0; m < d3; m++) {
                nr += Cc[j][l][m].real() * Cc[j][l][m].real();
                ni += Cc[j][l][m].imag() * Cc[j][l][m].imag();
            }
    bool useR = sqrt(nr) >= sqrt(ni);
    double nrm = sqrt(useR ? nr : ni);
    for (int j = 0; j < d1; j++)
        for (int l = 0; l < d2; l++)
            for (int m = 0; m < d3; m++)
                outv[(j * d2 + l) * d3 + m] =
                    (useR ? Cc[j][l][m].real() : Cc[j][l][m].imag()) / nrm;
}

static void build_params(Params& P) {
    static const int L1[NPATHS]   = {0,0,0,1,1,1,1,2,2,2,2};
    static const int L2[NPATHS]   = {0,1,2,0,1,1,2,0,1,2,2};
    static const int LOA[NPATHS]  = {0,1,2,1,0,2,1,2,1,0,2};
    static const int cof3[NPATHS] = {0,1,10,35,44,53,98,143,168,213,238};
    static const int x2off[3] = {0, 1, 4};
    const double pw[3] = { sqrt(1.0/384.0), sqrt(3.0/512.0), sqrt(5.0/512.0) };

    for (int p = 0; p < NPATHS; p++) {
        int d1 = 2*L1[p] + 1, d2 = 2*L2[p] + 1, d3 = 2*LOA[p] + 1;
        double buf[125];
        calc_w3j(L1[p], L2[p], LOA[p], buf);
        for (int idx = 0; idx < d1*d2*d3; idx++)
            P.C[cof3[p] + idx] = (float)(buf[idx] * pw[LOA[p]]);
    }
    int ci = 0;
    for (int p = 0; p < NPATHS; p++) {
        int d1 = 2*L1[p] + 1, d2 = 2*L2[p] + 1, d3 = 2*LOA[p] + 1;
        for (int i = 0; i < d1; i++)
            for (int k = 0; k < d3; k++)
                P.cmap[ci++] = make_int4(cof3[p] + i*d2*d3 + k, d2, d3,
                                         x2off[L2[p]]);
    }
}

extern "C" void kernel_launch(void* const* d_in, const int* in_sizes, int n_in,
                              void* d_out, int out_size)
{
    const float* x1  = (const float*)d_in[0];
    const float* x2  = (const float*)d_in[1];
    const float* wt  = (const float*)d_in[2];
    float*       out = (float*)d_out;
    const int N = in_sizes[0] / 1152;

    Params P;
    build_params(P);

    cudaFuncSetAttribute(fctp_gemm,
                         cudaFuncAttributeMaxDynamicSharedMemorySize, SMEM_TOTAL);

    const int NA = (N + 7) / 8;
    prep_kernel<<<NA + WPREP_BLOCKS, 256>>>(x1, x2, wt, N, NA, P);

    const int T0 = (N     + 63) / 64;
    const int T1 = (3 * N + 63) / 64;
    const int T2 = (5 * N + 63) / 64;
    fctp_gemm<<<T0 + T1 + T2, 256, SMEM_TOTAL>>>(out, N, T0, T1);
}